// round 7
// baseline (speedup 1.0000x reference)
#include <cuda_runtime.h>
#include <stdint.h>

#define NTHREADS 512
#define NN 32768
#define NBINS 4096
#define PRE_NMS_K 300
#define POST_KK 100
#define CAND_CAP 4096     /* smem selected-candidate cap */
#define CAND_GCAP 8192    /* global per-batch candidate cap */
#define MW 5              /* ceil(300/64) */
#define B_MAX 64
#define SCAN_PARTS 16

/* ---- global scratch (allowed: __device__ arrays) ---- */
__device__ unsigned long long g_cand[B_MAX * CAND_GCAP];
__device__ int g_cnt09[B_MAX];
__device__ int g_cnt005[B_MAX];

/* ---- finalize smem layout (bytes) ---- */
#define CANDR_OFF  0                               /* raw candidates  */
#define HIST_OFF   (CANDR_OFF + CAND_GCAP * 8)     /* 65536 */
#define CANDS_OFF  (HIST_OFF + NBINS * 4)          /* 81920 */
#define BX1_OFF    (CANDS_OFF + CAND_CAP * 8)      /* 114688 */
#define BY1_OFF    (BX1_OFF + PRE_NMS_K * 4)
#define BX2_OFF    (BY1_OFF + PRE_NMS_K * 4)
#define BY2_OFF    (BX2_OFF + PRE_NMS_K * 4)
#define BAREA_OFF  (BY2_OFF + PRE_NMS_K * 4)
#define MASK_OFF   (BAREA_OFF + PRE_NMS_K * 4)     /* pad to 8 */
#define MASK_OFF8  ((MASK_OFF + 7) & ~7)
#define KEEP_OFF   (MASK_OFF8 + PRE_NMS_K * MW * 8)
#define WS_OFF     (KEEP_OFF + MW * 8)
#define SCAL_OFF   (WS_OFF + 16 * 4)
#define SMEM_BYTES (SCAL_OFF + 8 * 4)

__global__ void zero_kernel() {
    int t = threadIdx.x;
    if (t < B_MAX) { g_cnt09[t] = 0; g_cnt005[t] = 0; }
}

__global__ void __launch_bounds__(NTHREADS)
scan_kernel(const float* __restrict__ cls_prob) {
    const int part = blockIdx.x;
    const int b    = blockIdx.y;
    const int tid  = threadIdx.x;
    const int lane = tid & 31;
    const int ITEMS = NN / SCAN_PARTS;          /* 2048 */
    const int jbase = part * ITEMS;
    const float4* cp4 = (const float4*)(cls_prob + (size_t)b * (NN * 2))
                        + (size_t)part * (ITEMS / 2);
    int c005 = 0;
#pragma unroll
    for (int k = 0; k < (ITEMS / 2) / NTHREADS; k++) {
        int m = tid + k * NTHREADS;
        float4 v = cp4[m];
        c005 += (v.y >= 0.05f) + (v.w >= 0.05f);
#pragma unroll
        for (int h = 0; h < 2; h++) {
            float s = h ? v.w : v.y;
            int j = jbase + 2 * m + h;
            bool p = (s >= 0.9f);
            unsigned ball = __ballot_sync(0xFFFFFFFFu, p);
            if (ball) {
                int base = 0;
                if (lane == 0) base = atomicAdd(&g_cnt09[b], __popc(ball));
                base = __shfl_sync(0xFFFFFFFFu, base, 0);
                if (p) {
                    int off = base + __popc(ball & ((1u << lane) - 1u));
                    if (off < CAND_GCAP)
                        g_cand[b * CAND_GCAP + off] =
                            ((unsigned long long)__float_as_uint(s) << 32) |
                            (unsigned long long)(0xFFFFFFFFu - (uint32_t)j);
                }
            }
        }
    }
#pragma unroll
    for (int off = 16; off >= 1; off >>= 1)
        c005 += __shfl_down_sync(0xFFFFFFFFu, c005, off);
    if (lane == 0 && c005) atomicAdd(&g_cnt005[b], c005);
}

__global__ void __launch_bounds__(NTHREADS, 1)
finalize_kernel(const float* __restrict__ cls_prob,
                const float* __restrict__ boxes,
                const float* __restrict__ deltas,
                const float* __restrict__ im_info,
                float* __restrict__ out)
{
    extern __shared__ unsigned char smem[];
    unsigned long long* candR = (unsigned long long*)(smem + CANDR_OFF);
    int*                hist  = (int*)(smem + HIST_OFF);
    unsigned long long* cand  = (unsigned long long*)(smem + CANDS_OFF);
    float*              bx1   = (float*)(smem + BX1_OFF);
    float*              by1   = (float*)(smem + BY1_OFF);
    float*              bx2   = (float*)(smem + BX2_OFF);
    float*              by2   = (float*)(smem + BY2_OFF);
    float*              barea = (float*)(smem + BAREA_OFF);
    unsigned long long* maskA = (unsigned long long*)(smem + MASK_OFF8);
    unsigned long long* keepw = (unsigned long long*)(smem + KEEP_OFF);
    int*                wsums = (int*)(smem + WS_OFF);
    int*                scal  = (int*)(smem + SCAL_OFF); /* 0=selCnt 1=bstar */

    const int b    = blockIdx.x;
    const int tid  = threadIdx.x;
    const int lane = tid & 31;
    const int wrp  = tid >> 5;

    const int cnt09r = g_cnt09[b];
    const int cnt005 = g_cnt005[b];
    const int n09 = cnt09r < CAND_GCAP ? cnt09r : CAND_GCAP;
    const int target0 = cnt005 < PRE_NMS_K ? cnt005 : PRE_NMS_K;
    const bool fast = (cnt09r >= target0) && (cnt09r <= CAND_GCAP);

    for (int i = tid; i < NBINS; i += NTHREADS) hist[i] = 0;
    if (tid == 0) { scal[0] = 0; scal[1] = NBINS; }
    __syncthreads();

    /* ---- build histogram ---- */
    if (fast) {
        for (int i = tid; i < n09; i += NTHREADS) {
            unsigned long long kk = g_cand[b * CAND_GCAP + i];
            candR[i] = kk;
            float s = __uint_as_float((uint32_t)(kk >> 32));
            int bin = (int)__fmul_rn(__fsub_rn(s, 0.9f), 40960.0f);
            bin = bin < NBINS - 1 ? bin : NBINS - 1;
            atomicAdd(&hist[bin], 1);
        }
    } else {
        const float2* cp = (const float2*)(cls_prob + (size_t)b * (NN * 2));
        for (int k = 0; k < NN / NTHREADS; k++) {
            int j = tid + k * NTHREADS;
            float s = cp[j].y;
            if (s >= 0.05f) {
                int bin = (int)__fmul_rn(__fsub_rn(s, 0.05f), (4096.0f / 0.95f));
                bin = bin < NBINS - 1 ? bin : NBINS - 1;
                atomicAdd(&hist[bin], 1);
            }
        }
    }
    __syncthreads();

    /* ---- chunk sums (top-down) + shfl block scan -> bstar ---- */
    int base8 = NBINS - 8 * (tid + 1);
    int4 h0 = *(int4*)&hist[base8];
    int4 h1 = *(int4*)&hist[base8 + 4];
    int s8 = h0.x + h0.y + h0.z + h0.w + h1.x + h1.y + h1.z + h1.w;
    int v = s8;
#pragma unroll
    for (int off = 1; off < 32; off <<= 1) {
        int n = __shfl_up_sync(0xFFFFFFFFu, v, off);
        if (lane >= off) v += n;
    }
    if (lane == 31) wsums[wrp] = v;
    __syncthreads();
    if (wrp == 0) {
        int t = (lane < 16) ? wsums[lane] : 0;
#pragma unroll
        for (int off = 1; off < 16; off <<= 1) {
            int n = __shfl_up_sync(0xFFFFFFFFu, t, off);
            if (lane >= off) t += n;
        }
        if (lane < 16) wsums[lane] = t;
    }
    __syncthreads();
    int inc = v + (wrp > 0 ? wsums[wrp - 1] : 0);
    int total = wsums[15];
    int target = total < PRE_NMS_K ? total : PRE_NMS_K;
    {
        int exc = inc - s8;
        if (target > 0 && exc < target && target <= inc) {
            int cum = exc, bsel = base8;
            for (int u = 7; u >= 0; u--) {
                cum += hist[base8 + u];
                if (cum >= target) { bsel = base8 + u; break; }
            }
            scal[1] = bsel;
        }
    }
    __syncthreads();
    int bstar = scal[1];

    /* ---- collect selected candidates ---- */
    if (fast) {
        for (int i = tid; i < n09; i += NTHREADS) {
            unsigned long long kk = candR[i];
            float s = __uint_as_float((uint32_t)(kk >> 32));
            int bin = (int)__fmul_rn(__fsub_rn(s, 0.9f), 40960.0f);
            bin = bin < NBINS - 1 ? bin : NBINS - 1;
            if (bin >= bstar) {
                int p = atomicAdd(&scal[0], 1);
                if (p < CAND_CAP) cand[p] = kk;
            }
        }
    } else {
        const float2* cp = (const float2*)(cls_prob + (size_t)b * (NN * 2));
        for (int k = 0; k < NN / NTHREADS; k++) {
            int j = tid + k * NTHREADS;
            float s = cp[j].y;
            if (s >= 0.05f) {
                int bin = (int)__fmul_rn(__fsub_rn(s, 0.05f), (4096.0f / 0.95f));
                bin = bin < NBINS - 1 ? bin : NBINS - 1;
                if (bin >= bstar) {
                    int p = atomicAdd(&scal[0], 1);
                    if (p < CAND_CAP)
                        cand[p] = ((unsigned long long)__float_as_uint(s) << 32) |
                                  (unsigned long long)(0xFFFFFFFFu - (uint32_t)j);
                }
            }
        }
    }
    __syncthreads();
    int cnt = scal[0] < CAND_CAP ? scal[0] : CAND_CAP;
    int M = 512;
    while (M < cnt) M <<= 1;
    for (int i = cnt + tid; i < M; i += NTHREADS) cand[i] = 0ull;
    __syncthreads();

    /* ---- Bitonic sort descending: (score desc, idx asc) == jax top_k order ---- */
    if (M == 512) {
        unsigned long long a = cand[tid];
#pragma unroll
        for (int k2 = 2; k2 <= 32; k2 <<= 1) {
#pragma unroll
            for (int jj = 16; jj >= 1; jj >>= 1) {
                if (jj <= (k2 >> 1)) {
                    unsigned long long c = __shfl_xor_sync(0xFFFFFFFFu, a, jj);
                    bool keepmax = (((tid & k2) == 0) == ((tid & jj) == 0));
                    unsigned long long mx = a > c ? a : c;
                    unsigned long long mn = a > c ? c : a;
                    a = keepmax ? mx : mn;
                }
            }
        }
        cand[tid] = a;
        __syncthreads();
        for (int k2 = 64; k2 <= 512; k2 <<= 1) {
            for (int jj = k2 >> 1; jj >= 32; jj >>= 1) {
                int l = tid ^ jj;
                if (l > tid) {
                    unsigned long long x = cand[tid];
                    unsigned long long y = cand[l];
                    bool up = ((tid & k2) == 0);
                    if (up ? (x < y) : (x > y)) { cand[tid] = y; cand[l] = x; }
                }
                __syncthreads();
            }
            a = cand[tid];
#pragma unroll
            for (int jj = 16; jj >= 1; jj >>= 1) {
                unsigned long long c = __shfl_xor_sync(0xFFFFFFFFu, a, jj);
                bool keepmax = (((tid & k2) == 0) == ((tid & jj) == 0));
                unsigned long long mx = a > c ? a : c;
                unsigned long long mn = a > c ? c : a;
                a = keepmax ? mx : mn;
            }
            cand[tid] = a;
            __syncthreads();
        }
    } else {
        for (int k2 = 2; k2 <= M; k2 <<= 1) {
            for (int jj = k2 >> 1; jj > 0; jj >>= 1) {
                for (int i = tid; i < M; i += NTHREADS) {
                    int l = i ^ jj;
                    if (l > i) {
                        unsigned long long a2 = cand[i];
                        unsigned long long c2 = cand[l];
                        bool up = ((i & k2) == 0);
                        if (up ? (a2 < c2) : (a2 > c2)) { cand[i] = c2; cand[l] = a2; }
                    }
                }
                __syncthreads();
            }
        }
    }

    int L = cnt < PRE_NMS_K ? cnt : PRE_NMS_K;

    /* ---- Decode + clip selected boxes (rn intrinsics: no FMA contraction) ---- */
    if (tid < L) {
        unsigned long long kk = cand[tid];
        int j = (int)(0xFFFFFFFFu - (uint32_t)(kk & 0xFFFFFFFFull));
        float4 bb = *(const float4*)(boxes  + ((size_t)b * NN + j) * 4);
        float4 dd = *(const float4*)(deltas + ((size_t)b * NN + j) * 4);
        float w  = __fadd_rn(__fsub_rn(bb.z, bb.x), 1.0f);
        float h  = __fadd_rn(__fsub_rn(bb.w, bb.y), 1.0f);
        float cx = __fadd_rn(bb.x, __fmul_rn(0.5f, w));
        float cy = __fadd_rn(bb.y, __fmul_rn(0.5f, h));
        float d0 = __fmul_rn(dd.x, 0.1f);
        float d1 = __fmul_rn(dd.y, 0.1f);
        float d2 = __fmul_rn(dd.z, 0.2f);
        float d3 = __fmul_rn(dd.w, 0.2f);
        float pcx = __fadd_rn(__fmul_rn(d0, w), cx);
        float pcy = __fadd_rn(__fmul_rn(d1, h), cy);
        float pw  = __fmul_rn((float)exp((double)d2), w);
        float ph  = __fmul_rn((float)exp((double)d3), h);
        float x1 = __fsub_rn(pcx, __fmul_rn(0.5f, pw));
        float y1 = __fsub_rn(pcy, __fmul_rn(0.5f, ph));
        float x2 = __fadd_rn(pcx, __fmul_rn(0.5f, pw));
        float y2 = __fadd_rn(pcy, __fmul_rn(0.5f, ph));
        float hmax = __fsub_rn(im_info[b * 3 + 0], 1.0f);
        float wmax = __fsub_rn(im_info[b * 3 + 1], 1.0f);
        x1 = fminf(fmaxf(x1, 0.0f), wmax);
        y1 = fminf(fmaxf(y1, 0.0f), hmax);
        x2 = fminf(fmaxf(x2, 0.0f), wmax);
        y2 = fminf(fmaxf(y2, 0.0f), hmax);
        bx1[tid] = x1; by1[tid] = y1; bx2[tid] = x2; by2[tid] = y2;
        barea[tid] = __fmul_rn(__fadd_rn(__fsub_rn(x2, x1), 1.0f),
                               __fadd_rn(__fsub_rn(y2, y1), 1.0f));
    }
    __syncthreads();

    /* ---- IoU suppression bitmasks: mask[i] bit j set iff j>i && iou>0.3 ---- */
    for (int item = tid; item < PRE_NMS_K * MW; item += NTHREADS) {
        int i = item / MW, w = item % MW;
        unsigned long long bits = 0ull;
        if (i < L) {
            float xi1 = bx1[i], yi1 = by1[i], xi2 = bx2[i], yi2 = by2[i], ai = barea[i];
            int j0 = w * 64;
            int jend = (j0 + 64 < L) ? j0 + 64 : L;
            for (int j = (j0 > i + 1 ? j0 : i + 1); j < jend; j++) {
                float xx1 = fmaxf(xi1, bx1[j]);
                float yy1 = fmaxf(yi1, by1[j]);
                float xx2 = fminf(xi2, bx2[j]);
                float yy2 = fminf(yi2, by2[j]);
                float iw = fmaxf(__fadd_rn(__fsub_rn(xx2, xx1), 1.0f), 0.0f);
                float ih = fmaxf(__fadd_rn(__fsub_rn(yy2, yy1), 1.0f), 0.0f);
                float inter = __fmul_rn(iw, ih);
                float uni = __fsub_rn(__fadd_rn(ai, barea[j]), inter);
                float iou = __fdiv_rn(inter, uni);
                if (iou > 0.3f) bits |= 1ull << (j - j0);
            }
        }
        maskA[item] = bits;
    }
    __syncthreads();

    /* ---- Serial greedy NMS, chunked to keep LDS off the decision chain ---- */
    if (tid == 0) {
        unsigned long long r[MW] = {0ull, 0ull, 0ull, 0ull, 0ull};
#pragma unroll
        for (int w = 0; w < MW; w++) {
            int i0w = w * 64;
            if (i0w < L) {
                int iend = (i0w + 64 < L) ? i0w + 64 : L;
                for (int c0 = i0w; c0 < iend; c0 += 16) {
                    int ce = (c0 + 16 < iend) ? c0 + 16 : iend;
                    unsigned long long mm[16];
#pragma unroll
                    for (int t = 0; t < 16; t++)
                        mm[t] = (c0 + t < ce) ? maskA[(c0 + t) * MW + w] : 0ull;
#pragma unroll
                    for (int t = 0; t < 16; t++) {
                        int i = c0 + t;
                        if (i < ce && !((r[w] >> (i - i0w)) & 1ull))
                            r[w] |= mm[t];
                    }
                }
                int nb = iend - i0w;
                unsigned long long vm = (nb >= 64) ? ~0ull : ((1ull << nb) - 1ull);
                unsigned long long kw = (~r[w]) & vm;
                while (kw) {
                    int t = __ffsll((long long)kw) - 1;
                    kw &= kw - 1ull;
                    const unsigned long long* m = maskA + (i0w + t) * MW;
#pragma unroll
                    for (int w2 = 0; w2 < MW; w2++)
                        if (w2 > w) r[w2] |= m[w2];
                }
            }
        }
#pragma unroll
        for (int w = 0; w < MW; w++) {
            int lo = w * 64;
            unsigned long long vm = (L <= lo) ? 0ull
                                  : ((L - lo >= 64) ? ~0ull : ((1ull << (L - lo)) - 1ull));
            keepw[w] = (~r[w]) & vm;
        }
    }
    __syncthreads();

    /* ---- Output: zero then scatter kept rows by rank ---- */
    float* outb = out + (size_t)b * (POST_KK * 5);
    for (int t = tid; t < POST_KK * 5; t += NTHREADS) outb[t] = 0.0f;
    __syncthreads();
    if (tid < L) {
        int w = tid >> 6, bp = tid & 63;
        if ((keepw[w] >> bp) & 1ull) {
            int rank = 0;
            for (int u = 0; u < w; u++) rank += __popcll(keepw[u]);
            rank += __popcll(keepw[w] & ((1ull << bp) - 1ull));
            if (rank < POST_KK) {
                float* row = outb + rank * 5;
                row[0] = (float)b;
                row[1] = bx1[tid];
                row[2] = by1[tid];
                row[3] = bx2[tid];
                row[4] = by2[tid];
            }
        }
    }
}

extern "C" void kernel_launch(void* const* d_in, const int* in_sizes, int n_in,
                              void* d_out, int out_size) {
    const float* cls_prob = (const float*)d_in[0];
    const float* boxes    = (const float*)d_in[1];
    const float* deltas   = (const float*)d_in[2];
    const float* im_info  = (const float*)d_in[3];
    int B = in_sizes[3] / 3;
    if (B > B_MAX) B = B_MAX;
    cudaFuncSetAttribute(finalize_kernel,
                         cudaFuncAttributeMaxDynamicSharedMemorySize, SMEM_BYTES);
    zero_kernel<<<1, 128>>>();
    scan_kernel<<<dim3(SCAN_PARTS, B), NTHREADS>>>(cls_prob);
    finalize_kernel<<<B, NTHREADS, SMEM_BYTES>>>(cls_prob, boxes, deltas,
                                                 im_info, (float*)d_out);
}